// round 1
// baseline (speedup 1.0000x reference)
#include <cuda_runtime.h>
#include <math.h>

#define Bsz 256
#define Tt  500
#define Ii  128
#define Hh  512
#define CLIPV 5.0f
#define KC 32

// Double-buffered hidden state (scratch via __device__ globals — no allocation).
__device__ float g_h[2][Bsz * Hh];

__global__ void init_h(const float* __restrict__ h0) {
    int i = blockIdx.x * blockDim.x + threadIdx.x;
    if (i < Bsz * Hh) g_h[0][i] = h0[i];
}

// After 500 steps (even), final h sits in g_h[0].
__global__ void copy_hlast(float* __restrict__ dst) {
    int i = blockIdx.x * blockDim.x + threadIdx.x;
    if (i < Bsz * Hh) dst[i] = g_h[0][i];
}

// One GRU timestep, fused: hg = h@w_hh^T (K=512) and xg = x_t@w_ih^T (K=128)
// plus gates + clip + output write. Output tile: 32 batch x 32 hidden.
__global__ void __launch_bounds__(256) gru_step(
    const float* __restrict__ x,      // (B, T, I)
    const float* __restrict__ w_ih,   // (3H, I)
    const float* __restrict__ w_hh,   // (3H, H)
    const float* __restrict__ b_ih,   // (3H)
    const float* __restrict__ b_hh,   // (3H)
    float* __restrict__ out,          // (B, T, H) then (B, H) tail
    int t)
{
    const float* __restrict__ h_in  = g_h[t & 1];
    float* __restrict__       h_out = g_h[(t + 1) & 1];

    // stride-33 padding -> conflict-free scattered stores and reads
    __shared__ float Hs[KC][33];        // A operand tile: [k][batch]
    __shared__ float Ws[3][KC][33];     // B operand tiles: [gate][k][m]

    const int tid = threadIdx.x;
    const int tx = tid & 15;            // hidden (m) direction
    const int ty = tid >> 4;            // batch  (b) direction
    const int m0 = blockIdx.x * 32;
    const int b0 = blockIdx.y * 32;

    // loader mapping: each thread loads one float4 per tile row-group
    const int lb = tid >> 3;            // row within tile (bb or mm): 0..31
    const int lk = (tid & 7) * 4;       // k offset: 0,4,...,28

    float accH[3][4];                   // h-side pre-activations (r, z, n)
    float accX[3][4];                   // x-side pre-activations (r, z, n)
    #pragma unroll
    for (int g = 0; g < 3; g++)
        #pragma unroll
        for (int i = 0; i < 4; i++) { accH[g][i] = 0.f; accX[g][i] = 0.f; }

    // ---------------- Phase 1: h_prev @ w_hh^T  (K = 512) ----------------
    for (int k0 = 0; k0 < Hh; k0 += KC) {
        float4 hv = *reinterpret_cast<const float4*>(&h_in[(b0 + lb) * Hh + k0 + lk]);
        Hs[lk + 0][lb] = hv.x; Hs[lk + 1][lb] = hv.y;
        Hs[lk + 2][lb] = hv.z; Hs[lk + 3][lb] = hv.w;
        #pragma unroll
        for (int g = 0; g < 3; g++) {
            float4 wv = *reinterpret_cast<const float4*>(
                &w_hh[(g * Hh + m0 + lb) * Hh + k0 + lk]);
            Ws[g][lk + 0][lb] = wv.x; Ws[g][lk + 1][lb] = wv.y;
            Ws[g][lk + 2][lb] = wv.z; Ws[g][lk + 3][lb] = wv.w;
        }
        __syncthreads();
        #pragma unroll
        for (int kk = 0; kk < KC; kk++) {
            float hv0 = Hs[kk][2 * ty];
            float hv1 = Hs[kk][2 * ty + 1];
            #pragma unroll
            for (int g = 0; g < 3; g++) {
                float w0 = Ws[g][kk][2 * tx];
                float w1 = Ws[g][kk][2 * tx + 1];
                accH[g][0] += hv0 * w0; accH[g][1] += hv0 * w1;
                accH[g][2] += hv1 * w0; accH[g][3] += hv1 * w1;
            }
        }
        __syncthreads();
    }

    // ---------------- Phase 2: x_t @ w_ih^T  (K = 128) ----------------
    for (int k0 = 0; k0 < Ii; k0 += KC) {
        float4 xv = *reinterpret_cast<const float4*>(
            &x[((size_t)(b0 + lb) * Tt + t) * Ii + k0 + lk]);
        Hs[lk + 0][lb] = xv.x; Hs[lk + 1][lb] = xv.y;
        Hs[lk + 2][lb] = xv.z; Hs[lk + 3][lb] = xv.w;
        #pragma unroll
        for (int g = 0; g < 3; g++) {
            float4 wv = *reinterpret_cast<const float4*>(
                &w_ih[(g * Hh + m0 + lb) * Ii + k0 + lk]);
            Ws[g][lk + 0][lb] = wv.x; Ws[g][lk + 1][lb] = wv.y;
            Ws[g][lk + 2][lb] = wv.z; Ws[g][lk + 3][lb] = wv.w;
        }
        __syncthreads();
        #pragma unroll
        for (int kk = 0; kk < KC; kk++) {
            float xv0 = Hs[kk][2 * ty];
            float xv1 = Hs[kk][2 * ty + 1];
            #pragma unroll
            for (int g = 0; g < 3; g++) {
                float w0 = Ws[g][kk][2 * tx];
                float w1 = Ws[g][kk][2 * tx + 1];
                accX[g][0] += xv0 * w0; accX[g][1] += xv0 * w1;
                accX[g][2] += xv1 * w0; accX[g][3] += xv1 * w1;
            }
        }
        __syncthreads();
    }

    // ---------------- Epilogue: gates, clip, write ----------------
    #pragma unroll
    for (int ib = 0; ib < 2; ib++) {
        const int b = b0 + 2 * ty + ib;
        #pragma unroll
        for (int im = 0; im < 2; im++) {
            const int m = m0 + 2 * tx + im;
            const int idx = ib * 2 + im;

            float pre_r = accX[0][idx] + accH[0][idx] + b_ih[m]      + b_hh[m];
            float pre_z = accX[1][idx] + accH[1][idx] + b_ih[Hh + m] + b_hh[Hh + m];
            float xn    = accX[2][idx] + b_ih[2 * Hh + m];
            float hn    = accH[2][idx] + b_hh[2 * Hh + m];

            float r = 1.f / (1.f + expf(-pre_r));
            float z = 1.f / (1.f + expf(-pre_z));
            float n = tanhf(xn + r * hn);

            float hp   = h_in[b * Hh + m];
            float hnew = (1.f - z) * n + z * hp;
            hnew = fminf(fmaxf(hnew, -CLIPV), CLIPV);

            h_out[b * Hh + m] = hnew;
            out[((size_t)b * Tt + t) * Hh + m] = hnew;
        }
    }
}

extern "C" void kernel_launch(void* const* d_in, const int* in_sizes, int n_in,
                              void* d_out, int out_size)
{
    (void)in_sizes; (void)n_in; (void)out_size;
    const float* x    = (const float*)d_in[0];
    const float* h0   = (const float*)d_in[1];
    const float* w_ih = (const float*)d_in[2];
    const float* w_hh = (const float*)d_in[3];
    const float* b_ih = (const float*)d_in[4];
    const float* b_hh = (const float*)d_in[5];
    float* out = (float*)d_out;

    init_h<<<(Bsz * Hh + 255) / 256, 256>>>(h0);

    dim3 grid(Hh / 32, Bsz / 32);   // 16 x 8 = 128 blocks
    for (int t = 0; t < Tt; t++) {
        gru_step<<<grid, 256>>>(x, w_ih, w_hh, b_ih, b_hh, out, t);
    }

    copy_hlast<<<(Bsz * Hh + 255) / 256, 256>>>(out + (size_t)Bsz * Tt * Hh);
}